// round 5
// baseline (speedup 1.0000x reference)
#include <cuda_runtime.h>
#include <math.h>

#define NSEG 256      // B*M
#define MLAB 32       // M
#define BSUB 8        // B
#define DELTA_V 0.5f
#define TWO_DELTA_D 3.0f

#define GRID 296      // 2 CTAs/SM * 148 SMs
#define TPB  512
#define PF   (12 * TPB)   // prefetch distance in points

// ---------------- device scratch (self-cleaning across graph replays) ----
__device__ float    g_sums[NSEG * 16] = {};
__device__ float    g_cnts[NSEG]      = {};
__device__ float    g_pull = 0.0f;
__device__ float    g_push = 0.0f;
__device__ unsigned g_bar1 = 0u;
__device__ unsigned g_bar2 = 0u;

#define SH_FLOATS (NSEG * 20 + NSEG + 256)

__device__ __forceinline__ void pf_l2(const void* p) {
    asm volatile("prefetch.global.L2 [%0];" :: "l"(p));
}

__device__ __forceinline__ float dot16(const float4& a, const float4& b,
                                       const float4& c, const float4& e) {
    return a.x*a.x + a.y*a.y + a.z*a.z + a.w*a.w
         + b.x*b.x + b.y*b.y + b.z*b.z + b.w*b.w
         + c.x*c.x + c.y*c.y + c.z*c.z + c.w*c.w
         + e.x*e.x + e.y*e.y + e.z*e.z + e.w*e.w;
}

__global__ __launch_bounds__(TPB, 2)
void k_fused(const float4* __restrict__ out4,
             const int* __restrict__ lab,
             const int* __restrict__ sbi,
             int n, float* __restrict__ out) {
    __shared__ float sh[SH_FLOATS];
    __shared__ int   sh_last;
    float* s_sum = sh;                 // stride 17 (phase A)
    float* s_mu  = sh;                 // stride 20 (phase C)
    float* s_cnt = sh + NSEG * 20;     // also s_iv in phase C
    float* s_red = sh + NSEG * 20 + NSEG;

    const int t  = threadIdx.x;
    const int bd = TPB;
    const int wid = t >> 5, lid = t & 31;

    // ---- chunk for this block ----
    int per = (n + GRID - 1) / GRID;
    per = ((per + bd - 1) / bd) * bd;
    int start = blockIdx.x * per;
    int end   = start + per; if (end > n) end = n;
    const int base  = start + t;
    const int iters = (end > start) ? (end - start) / bd : 0;

    // ================= PHASE A : segment sums of normalized x =============
    for (int i = t; i < NSEG * 17; i += bd) s_sum[i] = 0.0f;
    for (int i = t; i < NSEG; i += bd)      s_cnt[i] = 0.0f;
    __syncthreads();

    {
        float acc[16];
        float cnt = 0.0f;
        int   cur = -1;
#pragma unroll
        for (int d = 0; d < 16; d++) acc[d] = 0.0f;

        auto flush = [&]() {
            if (cur >= 0) {
#pragma unroll
                for (int d = 0; d < 16; d++) atomicAdd(&s_sum[cur * 17 + d], acc[d]);
                atomicAdd(&s_cnt[cur], cnt);
            }
        };
        auto accpt = [&](int seg, const float4& a, const float4& b,
                         const float4& c, const float4& e, float inv) {
            if (seg != cur) {
                flush();
                cur = seg; cnt = 0.0f;
#pragma unroll
                for (int d = 0; d < 16; d++) acc[d] = 0.0f;
            }
            acc[0]  += a.x * inv;  acc[1]  += a.y * inv;
            acc[2]  += a.z * inv;  acc[3]  += a.w * inv;
            acc[4]  += b.x * inv;  acc[5]  += b.y * inv;
            acc[6]  += b.z * inv;  acc[7]  += b.w * inv;
            acc[8]  += c.x * inv;  acc[9]  += c.y * inv;
            acc[10] += c.z * inv;  acc[11] += c.w * inv;
            acc[12] += e.x * inv;  acc[13] += e.y * inv;
            acc[14] += e.z * inv;  acc[15] += e.w * inv;
            cnt += 1.0f;
        };

        int i = 0;
        for (; i + 2 <= iters; i += 2) {      // 2-point batching for MLP
            int p0 = base + i * bd;
            int p1 = p0 + bd;
            // prefetch the stream PF points ahead (zero reg / scoreboard cost)
            int pf0 = p0 + PF;
            if (pf0 + bd < end) {
                pf_l2(out4 + (size_t)pf0 * 4);
                pf_l2(out4 + (size_t)(pf0 + bd) * 4);
                pf_l2(lab + pf0);
                pf_l2(sbi + pf0);
            }
            const float4* r0 = out4 + (size_t)p0 * 4;
            const float4* r1 = out4 + (size_t)p1 * 4;
            float4 a0 = r0[0], b0 = r0[1], c0 = r0[2], e0 = r0[3];
            float4 a1 = r1[0], b1 = r1[1], c1 = r1[2], e1 = r1[3];
            int l0 = lab[p0], s0 = sbi[p0];
            int l1 = lab[p1], s1 = sbi[p1];
            float inv0 = rsqrtf(dot16(a0, b0, c0, e0));
            float inv1 = rsqrtf(dot16(a1, b1, c1, e1));
            accpt(s0 * MLAB + l0, a0, b0, c0, e0, inv0);
            accpt(s1 * MLAB + l1, a1, b1, c1, e1, inv1);
        }
        for (; i < iters; i++) {
            int p = base + i * bd;
            const float4* r = out4 + (size_t)p * 4;
            float4 a = r[0], b = r[1], c = r[2], e = r[3];
            float inv = rsqrtf(dot16(a, b, c, e));
            accpt(sbi[p] * MLAB + lab[p], a, b, c, e, inv);
        }
        {   // ragged tail (not hit at these sizes)
            int p = start + iters * bd + t;
            if (p < end) {
                const float4* r = out4 + (size_t)p * 4;
                float4 a = r[0], b = r[1], c = r[2], e = r[3];
                float inv = rsqrtf(dot16(a, b, c, e));
                accpt(sbi[p] * MLAB + lab[p], a, b, c, e, inv);
            }
        }
        flush();
    }
    __syncthreads();

    // block flush -> global atomics
    for (int s = t; s < NSEG; s += bd) {
        float c0 = s_cnt[s];
        if (c0 != 0.0f) {
            atomicAdd(&g_cnts[s], c0);
#pragma unroll
            for (int d = 0; d < 16; d++)
                atomicAdd(&g_sums[s * 16 + d], s_sum[s * 17 + d]);
        }
    }

    // ================= GRID BARRIER =================
    __threadfence();
    __syncthreads();
    if (t == 0) {
        atomicAdd(&g_bar1, 1u);
        while (*(volatile unsigned*)&g_bar1 < (unsigned)GRID) { __nanosleep(64); }
    }
    __syncthreads();
    __threadfence();

    // ================= PHASE B : centroids (replicated per block) =========
    if (t < NSEG) {
        float c  = __ldcg(&g_cnts[t]);
        float ic = 1.0f / c;
        const float4* gs = (const float4*)&g_sums[t * 16];
        float4 m0 = __ldcg(gs + 0), m1 = __ldcg(gs + 1),
               m2 = __ldcg(gs + 2), m3 = __ldcg(gs + 3);
        float4* sm = (float4*)&s_mu[t * 20];
        m0.x *= ic; m0.y *= ic; m0.z *= ic; m0.w *= ic;
        m1.x *= ic; m1.y *= ic; m1.z *= ic; m1.w *= ic;
        m2.x *= ic; m2.y *= ic; m2.z *= ic; m2.w *= ic;
        m3.x *= ic; m3.y *= ic; m3.z *= ic; m3.w *= ic;
        sm[0] = m0; sm[1] = m1; sm[2] = m2; sm[3] = m3;
        s_cnt[t] = 1.0f / ((float)MLAB * c);    // s_iv
    }
    __syncthreads();

    // push term: block 0 only
    if (blockIdx.x == 0) {
        float h = 0.0f;
        if (t < NSEG) {
            int b = t >> 5, ii = t & 31;
            const float* mi = &s_mu[t * 20];
            for (int j = 0; j < MLAB; j++) {
                if (j == ii) continue;
                const float* mj = &s_mu[(b * 32 + j) * 20];
                float pd = 0.0f;
#pragma unroll
                for (int d = 0; d < 16; d++) pd += fabsf(mi[d] - mj[d]);
                float tt = TWO_DELTA_D - pd;
                if (tt > 0.0f) h += tt * tt;
            }
        }
        for (int off = 16; off > 0; off >>= 1)
            h += __shfl_down_sync(0xFFFFFFFFu, h, off);
        if (lid == 0) s_red[wid] = h;
        __syncthreads();
        if (t == 0) {
            float v = 0.0f;
            for (int w = 0; w < TPB / 32; w++) v += s_red[w];
            g_push = v / ((float)MLAB * (float)(MLAB - 1));
        }
        __syncthreads();
    }

    // ================= PHASE C : pull term (reverse walk, hot cache) ======
    float local = 0.0f;
    {
        auto ppt = [&](int seg, const float4& a, const float4& b,
                       const float4& c, const float4& e, float inv) {
            const float4* m4 = (const float4*)&s_mu[seg * 20];
            float4 m0 = m4[0], m1 = m4[1], m2 = m4[2], m3 = m4[3];
            float dist =
                  fabsf(fmaf(a.x, inv, -m0.x)) + fabsf(fmaf(a.y, inv, -m0.y))
                + fabsf(fmaf(a.z, inv, -m0.z)) + fabsf(fmaf(a.w, inv, -m0.w))
                + fabsf(fmaf(b.x, inv, -m1.x)) + fabsf(fmaf(b.y, inv, -m1.y))
                + fabsf(fmaf(b.z, inv, -m1.z)) + fabsf(fmaf(b.w, inv, -m1.w))
                + fabsf(fmaf(c.x, inv, -m2.x)) + fabsf(fmaf(c.y, inv, -m2.y))
                + fabsf(fmaf(c.z, inv, -m2.z)) + fabsf(fmaf(c.w, inv, -m2.w))
                + fabsf(fmaf(e.x, inv, -m3.x)) + fabsf(fmaf(e.y, inv, -m3.y))
                + fabsf(fmaf(e.z, inv, -m3.z)) + fabsf(fmaf(e.w, inv, -m3.w));
            float tt = dist - DELTA_V;
            if (tt > 0.0f) local += tt * tt * s_cnt[seg];   // s_iv
        };

        {   // ragged tail first
            int p = start + iters * bd + t;
            if (p < end) {
                const float4* r = out4 + (size_t)p * 4;
                float4 a = r[0], b = r[1], c = r[2], e = r[3];
                float inv = rsqrtf(dot16(a, b, c, e));
                ppt(sbi[p] * MLAB + lab[p], a, b, c, e, inv);
            }
        }
        int i = iters;
        while (i >= 2) {               // reverse: most-recently-streamed first
            i -= 2;
            int p0 = base + i * bd;
            int p1 = p0 + bd;
            // prefetch backwards PF points (cold once we leave the L2-hot tail)
            int pfp = p0 - PF;
            if (pfp >= start) {
                pf_l2(out4 + (size_t)pfp * 4);
                pf_l2(out4 + (size_t)(pfp + bd) * 4);
                pf_l2(lab + pfp);
                pf_l2(sbi + pfp);
            }
            const float4* r0 = out4 + (size_t)p0 * 4;
            const float4* r1 = out4 + (size_t)p1 * 4;
            float4 a1 = r1[0], b1 = r1[1], c1 = r1[2], e1 = r1[3];
            float4 a0 = r0[0], b0 = r0[1], c0 = r0[2], e0 = r0[3];
            int l1 = lab[p1], s1 = sbi[p1];
            int l0 = lab[p0], s0 = sbi[p0];
            float inv1 = rsqrtf(dot16(a1, b1, c1, e1));
            float inv0 = rsqrtf(dot16(a0, b0, c0, e0));
            ppt(s1 * MLAB + l1, a1, b1, c1, e1, inv1);
            ppt(s0 * MLAB + l0, a0, b0, c0, e0, inv0);
        }
        if (i == 1) {
            int p = base;
            const float4* r = out4 + (size_t)p * 4;
            float4 a = r[0], b = r[1], c = r[2], e = r[3];
            float inv = rsqrtf(dot16(a, b, c, e));
            ppt(sbi[p] * MLAB + lab[p], a, b, c, e, inv);
        }
    }

    // block reduction of pull
    for (int off = 16; off > 0; off >>= 1)
        local += __shfl_down_sync(0xFFFFFFFFu, local, off);
    if (lid == 0) s_red[wid] = local;
    __syncthreads();
    if (t == 0) {
        float v = 0.0f;
        for (int w = 0; w < TPB / 32; w++) v += s_red[w];
        atomicAdd(&g_pull, v);
    }

    // ================= EXIT: last block finalizes + resets ================
    if (t == 0) {
        __threadfence();
        unsigned old = atomicAdd(&g_bar2, 1u);
        sh_last = (old == (unsigned)GRID - 1u) ? 1 : 0;
    }
    __syncthreads();
    if (sh_last) {
        for (int i = t; i < NSEG * 16; i += bd) g_sums[i] = 0.0f;
        for (int i = t; i < NSEG; i += bd)      g_cnts[i] = 0.0f;
        if (t == 0) {
            float pull = atomicAdd(&g_pull, 0.0f);
            float push = g_push;
            out[0] = (pull + push) * (1.0f / (float)BSUB);
            g_pull = 0.0f;
            g_push = 0.0f;
            g_bar1 = 0u;
            g_bar2 = 0u;
        }
    }
}

extern "C" void kernel_launch(void* const* d_in, const int* in_sizes, int n_in,
                              void* d_out, int out_size) {
    const float4* out4 = (const float4*)d_in[0];
    const int*    lab  = (const int*)d_in[1];
    const int*    sbi  = (const int*)d_in[2];
    float* out = (float*)d_out;
    int n = in_sizes[1];   // N points

    k_fused<<<GRID, TPB>>>(out4, lab, sbi, n, out);
}